// round 8
// baseline (speedup 1.0000x reference)
#include <cuda_runtime.h>
#include <cuda_bf16.h>
#include <cstdint>

#define B_ 256
#define L_ 512
#define H_ 768
#define K_ 64
#define M_ (B_*L_)

#define LOG2E 1.4426950408889634f
#define LN2   0.6931471805599453f
#define ESHIFT 6.0f

// -------- device scratch --------
__device__ float          g_emit2[M_*K_];     // emit * log2(e)
__device__ float          g_Tt2[K_*K_];       // Tt2[j][k] = T[k][j]*log2e (gold score)
__device__ float          g_Et[K_*K_];        // Et[j][i]  = 2^(T[i][j]*log2e - 6)
__device__ __nv_bfloat16  g_Wt[K_*H_];        // W^T bf16 [n][h]
__device__ int            g_tags[M_];
__device__ int            g_len[B_];
__device__ int            g_cnt[B_];          // per-batch tile completion counter
__device__ int            g_tagmode;
__device__ int            g_maskmode;

__device__ __forceinline__ float ex2f(float x){ float y; asm("ex2.approx.ftz.f32 %0, %1;" : "=f"(y) : "f"(x)); return y; }
__device__ __forceinline__ float lg2f(float x){ float y; asm("lg2.approx.f32 %0, %1;"     : "=f"(y) : "f"(x)); return y; }
__device__ __forceinline__ float rcpf(float x){ float y; asm("rcp.approx.ftz.f32 %0, %1;" : "=f"(y) : "f"(x)); return y; }
#define BAR128() asm volatile("bar.sync 1, 128;" ::: "memory")

// ---------------------------------------------------------------
__global__ void detect_kernel(const unsigned int* __restrict__ tagw,
                              const unsigned char* __restrict__ maskb)
{
    __shared__ int any;
    if (threadIdx.x == 0) any = 0;
    __syncthreads();
    unsigned int w = tagw[2 * threadIdx.x + 1];
    if (w) atomicExch(&any, 1);
    __syncthreads();
    if (threadIdx.x == 0) {
        g_tagmode  = any ? 0 : 1;
        g_maskmode = (maskb[1] != 0) ? 0 : 1;
    }
}

__global__ __launch_bounds__(256)
void convert_kernel(const int* __restrict__ tagsraw,
                    const unsigned char* __restrict__ maskraw)
{
    __shared__ int s_red[8];
    const int b   = blockIdx.x;
    const int tid = threadIdx.x;
    const int tm  = g_tagmode;
    const int mm  = g_maskmode;

    if (tid == 0) g_cnt[b] = 0;            // reset handoff counters every replay

    for (int t = tid; t < L_; t += 256) {
        long idx = (long)b * L_ + t;
        g_tags[idx] = (tm == 1) ? tagsraw[2 * idx] : tagsraw[idx];
    }
    int cnt = 0;
    if (mm == 0) {
        const unsigned char* mb = maskraw + (size_t)b * L_;
        for (int t = tid; t < L_; t += 256) cnt += (mb[t] != 0);
    } else {
        const unsigned int* mw = ((const unsigned int*)maskraw) + (size_t)b * L_;
        for (int t = tid; t < L_; t += 256) cnt += (mw[t] != 0);
    }
#pragma unroll
    for (int o = 16; o > 0; o >>= 1) cnt += __shfl_xor_sync(0xffffffffu, cnt, o);
    if ((tid & 31) == 0) s_red[tid >> 5] = cnt;
    __syncthreads();
    if (tid == 0) {
        int s = 0;
#pragma unroll
        for (int i = 0; i < 8; ++i) s += s_red[i];
        g_len[b] = s;
    }
}

// ---------------------------------------------------------------
__global__ void prep_kernel(const float* __restrict__ W, const float* __restrict__ T)
{
    int idx    = blockIdx.x * blockDim.x + threadIdx.x;
    int stride = gridDim.x * blockDim.x;
    for (int i = idx; i < K_*H_; i += stride) {
        int n = i / H_, h = i - n*H_;
        g_Wt[i] = __float2bfloat16(W[h*K_ + n]);
    }
    for (int i = idx; i < K_*K_; i += stride) {
        int j = i >> 6, k = i & 63;
        float t2 = T[k*K_ + j] * LOG2E;
        g_Tt2[i] = t2;
        g_Et[i]  = ex2f(t2 - ESHIFT);
    }
}

// ---------------------------------------------------------------
// FUSED kernel: GEMM tile (blocks 4b..4b+3 cover batch b); the block that
// completes the batch's 4th tile runs the CRF. launch_bounds(256,3) caps
// regs (~85) so 3 GEMM blocks co-reside and a lingering owner only costs
// one slot (3 -> 2), not half the SM.
#define BM     128
#define BK     32
#define NITER  (H_/BK)   // 24
#define APITCH 40

__global__ __launch_bounds__(256, 3)
void fused_kernel(const float* __restrict__ F, const float* __restrict__ bias,
                  float* __restrict__ out)
{
    __shared__ __nv_bfloat16 Ash[2][BM * APITCH];
    __shared__ __nv_bfloat16 Bsh[2][K_ * APITCH];
    __shared__ float s_red[8];
    __shared__ float ds[2][K_];
    __shared__ float s_score;
    __shared__ int   s_owner;

    const int tid  = threadIdx.x;
    const int lane = tid & 31;
    const int warp = tid >> 5;
    const int wm   = warp & 3;
    const int wn   = warp >> 2;
    const int rowBase = blockIdx.x * BM;

    // ================= GEMM phase =================
    {
        float acc[2][4][4];
#pragma unroll
        for (int mi = 0; mi < 2; ++mi)
#pragma unroll
            for (int ni = 0; ni < 4; ++ni)
#pragma unroll
                for (int q = 0; q < 4; ++q) acc[mi][ni][q] = 0.f;

        const int aRow = tid >> 3;
        const int aKv  = tid & 7;
        const int bN   = tid >> 2;
        const int bKv  = tid & 3;
        const int g  = lane >> 2;
        const int tq = lane & 3;

        float4 av[4];
        int4   bv;
#pragma unroll
        for (int p = 0; p < 4; ++p)
            av[p] = *reinterpret_cast<const float4*>(
                F + (size_t)(rowBase + aRow + p*32) * H_ + aKv * 4);
        bv = *reinterpret_cast<const int4*>(g_Wt + bN*H_ + bKv*8);

#pragma unroll 1
        for (int k = 0; k < NITER; ++k) {
            const int cur = k & 1;
#pragma unroll
            for (int p = 0; p < 4; ++p) {
                int r = aRow + p * 32;
                __nv_bfloat162 h0 = __floats2bfloat162_rn(av[p].x, av[p].y);
                __nv_bfloat162 h1 = __floats2bfloat162_rn(av[p].z, av[p].w);
                *reinterpret_cast<__nv_bfloat162*>(&Ash[cur][r*APITCH + aKv*4    ]) = h0;
                *reinterpret_cast<__nv_bfloat162*>(&Ash[cur][r*APITCH + aKv*4 + 2]) = h1;
            }
            *reinterpret_cast<int4*>(&Bsh[cur][bN*APITCH + bKv*8]) = bv;
            __syncthreads();

            if (k + 1 < NITER) {
                const int kb = (k + 1) * BK;
#pragma unroll
                for (int p = 0; p < 4; ++p)
                    av[p] = *reinterpret_cast<const float4*>(
                        F + (size_t)(rowBase + aRow + p*32) * H_ + kb + aKv * 4);
                bv = *reinterpret_cast<const int4*>(g_Wt + bN*H_ + kb + bKv*8);
            }

#pragma unroll
            for (int ks = 0; ks < 2; ++ks) {
                uint32_t afr[2][4], bfr[4][2];
                const int c = ks*16 + tq*2;
#pragma unroll
                for (int mi = 0; mi < 2; ++mi) {
                    int r = wm*32 + mi*16 + g;
                    afr[mi][0] = *reinterpret_cast<const uint32_t*>(&Ash[cur][ r     *APITCH + c    ]);
                    afr[mi][1] = *reinterpret_cast<const uint32_t*>(&Ash[cur][(r + 8)*APITCH + c    ]);
                    afr[mi][2] = *reinterpret_cast<const uint32_t*>(&Ash[cur][ r     *APITCH + c + 8]);
                    afr[mi][3] = *reinterpret_cast<const uint32_t*>(&Ash[cur][(r + 8)*APITCH + c + 8]);
                }
#pragma unroll
                for (int ni = 0; ni < 4; ++ni) {
                    int n = wn*32 + ni*8 + g;
                    bfr[ni][0] = *reinterpret_cast<const uint32_t*>(&Bsh[cur][n*APITCH + c    ]);
                    bfr[ni][1] = *reinterpret_cast<const uint32_t*>(&Bsh[cur][n*APITCH + c + 8]);
                }
#pragma unroll
                for (int mi = 0; mi < 2; ++mi)
#pragma unroll
                    for (int ni = 0; ni < 4; ++ni) {
                        asm volatile(
                            "mma.sync.aligned.m16n8k16.row.col.f32.bf16.bf16.f32 "
                            "{%0,%1,%2,%3}, {%4,%5,%6,%7}, {%8,%9}, {%0,%1,%2,%3};"
                            : "+f"(acc[mi][ni][0]), "+f"(acc[mi][ni][1]),
                              "+f"(acc[mi][ni][2]), "+f"(acc[mi][ni][3])
                            : "r"(afr[mi][0]), "r"(afr[mi][1]), "r"(afr[mi][2]), "r"(afr[mi][3]),
                              "r"(bfr[ni][0]), "r"(bfr[ni][1]));
                    }
            }
            __syncthreads();
        }

#pragma unroll
        for (int mi = 0; mi < 2; ++mi) {
#pragma unroll
            for (int ni = 0; ni < 4; ++ni) {
                int col = wn*32 + ni*8 + tq*2;
                float b0 = bias[col], b1 = bias[col + 1];
                int r0 = rowBase + wm*32 + mi*16 + g;
                float2 v0 = make_float2((acc[mi][ni][0] + b0) * LOG2E,
                                        (acc[mi][ni][1] + b1) * LOG2E);
                float2 v1 = make_float2((acc[mi][ni][2] + b0) * LOG2E,
                                        (acc[mi][ni][3] + b1) * LOG2E);
                *reinterpret_cast<float2*>(&g_emit2[(size_t) r0      * K_ + col]) = v0;
                *reinterpret_cast<float2*>(&g_emit2[(size_t)(r0 + 8) * K_ + col]) = v1;
            }
        }
    }

    // ================= handoff =================
    const int b = blockIdx.x >> 2;
    __threadfence();                 // release this block's emit tile
    __syncthreads();
    if (tid == 0) s_owner = (atomicAdd(&g_cnt[b], 1) == 3);
    __syncthreads();
    if (!s_owner) return;
    __threadfence();                 // acquire peer tiles

    // ================= CRF phase (owner block only) =================
    const int len = g_len[b];
    const int*   tg = g_tags + (size_t)b * L_;
    const float* eb = g_emit2 + (size_t)b * L_ * K_;

    // ---- gold path score with all 256 threads ----
    {
        float sc = 0.f;
        for (int t = tid; t < len; t += 256) {
            int kt = tg[t];
            sc += eb[t * K_ + kt];
            if (t >= 1) sc += g_Tt2[kt * K_ + tg[t - 1]];
        }
#pragma unroll
        for (int o = 16; o > 0; o >>= 1) sc += __shfl_xor_sync(0xffffffffu, sc, o);
        if (lane == 0) s_red[warp] = sc;
        __syncthreads();
        if (tid == 0) {
            float s = 0.f;
#pragma unroll
            for (int i = 0; i < 8; ++i) s += s_red[i];
            s_score = s;
        }
        __syncthreads();
    }

    if (tid >= 128) return;          // recursion: warps 0-3 (bar.sync 1,128)
    const int j    = tid >> 1;       // output state
    const int half = tid & 1;        // source half (32 states)

    // ---- E half-rows in registers: Erow[i] = 2^(T2[half*32+i][j]-6) ----
    float Erow[32];
    {
        const float4* tp = reinterpret_cast<const float4*>(g_Et + j * K_ + half * 32);
#pragma unroll
        for (int q = 0; q < 8; ++q) {
            float4 v = tp[q];
            Erow[4*q] = v.x; Erow[4*q+1] = v.y; Erow[4*q+2] = v.z; Erow[4*q+3] = v.w;
        }
    }

    if (half == 0) ds[0][j] = ex2f(eb[j]);
    float C = 0.f;
    float ebuf[8];
#pragma unroll
    for (int q = 0; q < 8; ++q) ebuf[q] = eb[(q + 1) * K_ + j];   // len >= 128
    BAR128();

    int cur = 0;

    auto STEP = [&](int t, int slot, bool renorm, bool use_ring) {
        float ev;
        if (use_ring) {
            ev = ebuf[slot];
            int tn = t + 8; if (tn > L_ - 1) tn = L_ - 1;
            ebuf[slot] = eb[tn * K_ + j];
        } else {
            ev = eb[t * K_ + j];
        }
        const float se = ex2f(ev);

        const float4* p4 = reinterpret_cast<const float4*>(&ds[cur][half * 32]);
        float a0=0.f, a1=0.f, a2=0.f, a3=0.f;
        float mA = 0.f, mB = 0.f;     // streamed max over own half (values >= 0)
#pragma unroll
        for (int q = 0; q < 8; ++q) {
            float4 v = p4[q];
            a0 = fmaf(v.x, Erow[4*q    ], a0);
            a1 = fmaf(v.y, Erow[4*q + 1], a1);
            a2 = fmaf(v.z, Erow[4*q + 2], a2);
            a3 = fmaf(v.w, Erow[4*q + 3], a3);
            if (renorm) {
                float mv = fmaxf(fmaxf(v.x, v.y), fmaxf(v.z, v.w));
                if (q & 1) mB = fmaxf(mB, mv); else mA = fmaxf(mA, mv);
            }
        }
        float acc = (a0 + a1) + (a2 + a3);
        acc += __shfl_xor_sync(0xffffffffu, acc, 1);   // combine halves
        float dn = acc * se;

        if (renorm) {
            float m = fmaxf(mA, mB);
            m = fmaxf(m, __shfl_xor_sync(0xffffffffu, m, 1));  // full 64-state max
            m = fmaxf(m, 1e-30f);
            dn *= rcpf(m);
            C += lg2f(m);
        }
        if (half == 0) ds[cur ^ 1][j] = dn;
        BAR128();
        cur ^= 1;
    };

    // head peel t=1..7
#pragma unroll
    for (int t = 1; t <= 7; ++t) STEP(t, t - 1, false, true);

    // main chunks of 8 (renorm at i==0 -> t % 8 == 0)
    int tb = 8;
    for (; tb + 8 <= len; tb += 8) {
#pragma unroll
        for (int i = 0; i < 8; ++i)
            STEP(tb + i, (i + 7) & 7, i == 0, true);
    }
    // tail: direct loads
    for (int t = tb; t < len; ++t)
        STEP(t, 0, (t & 7) == 0, false);

    // ---- final logsumexp over 64 states ----
    float v = (half == 0) ? ds[cur][j] : 0.f;
#pragma unroll
    for (int o = 16; o > 0; o >>= 1) v += __shfl_xor_sync(0xffffffffu, v, o);
    if (lane == 0) s_red[warp] = v;   // warps 0..3
    BAR128();
    if (tid == 0) {
        const float S = (s_red[0] + s_red[1]) + (s_red[2] + s_red[3]);
        const float logz2 = C + ESHIFT * (float)(len - 1) + lg2f(S);
        out[b] = (logz2 - s_score) * LN2;
    }
}

// ---------------------------------------------------------------
extern "C" void kernel_launch(void* const* d_in, const int* in_sizes, int n_in,
                              void* d_out, int out_size)
{
    const float*         features = (const float*)d_in[0];
    const float*         W        = (const float*)d_in[1];
    const float*         bias     = (const float*)d_in[2];
    const float*         trans    = (const float*)d_in[3];
    const int*           tagsraw  = (const int*)d_in[4];
    const unsigned char* maskraw  = (const unsigned char*)d_in[5];
    float*               out      = (float*)d_out;

    detect_kernel<<<1, 256>>>((const unsigned int*)tagsraw, maskraw);
    convert_kernel<<<B_, 256>>>(tagsraw, maskraw);
    prep_kernel<<<192, 256>>>(W, trans);
    fused_kernel<<<M_ / BM, 256>>>(features, bias, out);
}

// round 9
// speedup vs baseline: 1.0331x; 1.0331x over previous
#include <cuda_runtime.h>
#include <cuda_bf16.h>
#include <cstdint>

#define B_ 256
#define L_ 512
#define H_ 768
#define K_ 64
#define M_ (B_*L_)

#define LOG2E 1.4426950408889634f
#define LN2   0.6931471805599453f
#define ESHIFT 6.0f

// -------- device scratch --------
__device__ float          g_emit2[M_*K_];     // emit * log2(e)
__device__ float          g_Tt2[K_*K_];       // Tt2[j][k] = T[k][j]*log2e (gold score)
__device__ float          g_Et[K_*K_];        // Et[j][i]  = 2^(T[i][j]*log2e - 6)
__device__ __nv_bfloat16  g_Wt[K_*H_];        // W^T bf16 [n][h]
__device__ int            g_tags[M_];
__device__ int            g_len[B_];
__device__ int            g_cnt[B_];          // per-batch tile completion counter
__device__ int            g_tagmode;
__device__ int            g_maskmode;

__device__ __forceinline__ float ex2f(float x){ float y; asm("ex2.approx.ftz.f32 %0, %1;" : "=f"(y) : "f"(x)); return y; }
__device__ __forceinline__ float lg2f(float x){ float y; asm("lg2.approx.f32 %0, %1;"     : "=f"(y) : "f"(x)); return y; }
__device__ __forceinline__ float rcpf(float x){ float y; asm("rcp.approx.ftz.f32 %0, %1;" : "=f"(y) : "f"(x)); return y; }
#define BAR128() asm volatile("bar.sync 1, 128;" ::: "memory")

// ---------------------------------------------------------------
__global__ void detect_kernel(const unsigned int* __restrict__ tagw,
                              const unsigned char* __restrict__ maskb)
{
    __shared__ int any;
    if (threadIdx.x == 0) any = 0;
    __syncthreads();
    unsigned int w = tagw[2 * threadIdx.x + 1];
    if (w) atomicExch(&any, 1);
    __syncthreads();
    if (threadIdx.x == 0) {
        g_tagmode  = any ? 0 : 1;
        g_maskmode = (maskb[1] != 0) ? 0 : 1;
    }
}

// convert tags/lengths AND do the W/T prep (folded to save a launch)
__global__ __launch_bounds__(256)
void convert_kernel(const int* __restrict__ tagsraw,
                    const unsigned char* __restrict__ maskraw,
                    const float* __restrict__ W,
                    const float* __restrict__ T)
{
    __shared__ int s_red[8];
    const int b   = blockIdx.x;
    const int tid = threadIdx.x;
    const int tm  = g_tagmode;
    const int mm  = g_maskmode;

    if (tid == 0) g_cnt[b] = 0;            // reset handoff counters every replay

    for (int t = tid; t < L_; t += 256) {
        long idx = (long)b * L_ + t;
        g_tags[idx] = (tm == 1) ? tagsraw[2 * idx] : tagsraw[idx];
    }
    int cnt = 0;
    if (mm == 0) {
        const unsigned char* mb = maskraw + (size_t)b * L_;
        for (int t = tid; t < L_; t += 256) cnt += (mb[t] != 0);
    } else {
        const unsigned int* mw = ((const unsigned int*)maskraw) + (size_t)b * L_;
        for (int t = tid; t < L_; t += 256) cnt += (mw[t] != 0);
    }
#pragma unroll
    for (int o = 16; o > 0; o >>= 1) cnt += __shfl_xor_sync(0xffffffffu, cnt, o);
    if ((tid & 31) == 0) s_red[tid >> 5] = cnt;
    __syncthreads();
    if (tid == 0) {
        int s = 0;
#pragma unroll
        for (int i = 0; i < 8; ++i) s += s_red[i];
        g_len[b] = s;
    }

    // ---- prep, strided across the whole grid ----
    const int gidx    = b * 256 + tid;
    const int gstride = B_ * 256;
    for (int i = gidx; i < K_*H_; i += gstride) {
        int n = i / H_, h = i - n*H_;
        g_Wt[i] = __float2bfloat16(W[h*K_ + n]);
    }
    for (int i = gidx; i < K_*K_; i += gstride) {
        int j = i >> 6, k = i & 63;
        float t2 = T[k*K_ + j] * LOG2E;
        g_Tt2[i] = t2;
        g_Et[i]  = ex2f(t2 - ESHIFT);
    }
}

// ---------------------------------------------------------------
// FUSED kernel: GEMM tile (blocks 4b..4b+3 cover batch b); the block that
// completes the batch's 4th tile runs the CRF. No occupancy cap: the GEMM
// phase sets the register count (~88) and must not spill; the 128-thread
// CRF only needs Erow[32] so it doesn't inflate it.
#define BM     128
#define BK     32
#define NITER  (H_/BK)   // 24
#define APITCH 40

__global__ __launch_bounds__(256)
void fused_kernel(const float* __restrict__ F, const float* __restrict__ bias,
                  float* __restrict__ out)
{
    __shared__ __nv_bfloat16 Ash[2][BM * APITCH];
    __shared__ __nv_bfloat16 Bsh[2][K_ * APITCH];
    __shared__ float s_red[8];
    __shared__ float ds[2][K_];
    __shared__ float s_score;
    __shared__ int   s_owner;

    const int tid  = threadIdx.x;
    const int lane = tid & 31;
    const int warp = tid >> 5;
    const int wm   = warp & 3;
    const int wn   = warp >> 2;
    const int rowBase = blockIdx.x * BM;

    // ================= GEMM phase =================
    {
        float acc[2][4][4];
#pragma unroll
        for (int mi = 0; mi < 2; ++mi)
#pragma unroll
            for (int ni = 0; ni < 4; ++ni)
#pragma unroll
                for (int q = 0; q < 4; ++q) acc[mi][ni][q] = 0.f;

        const int aRow = tid >> 3;
        const int aKv  = tid & 7;
        const int bN   = tid >> 2;
        const int bKv  = tid & 3;
        const int g  = lane >> 2;
        const int tq = lane & 3;

        float4 av[4];
        int4   bv;
#pragma unroll
        for (int p = 0; p < 4; ++p)
            av[p] = *reinterpret_cast<const float4*>(
                F + (size_t)(rowBase + aRow + p*32) * H_ + aKv * 4);
        bv = *reinterpret_cast<const int4*>(g_Wt + bN*H_ + bKv*8);

#pragma unroll 1
        for (int k = 0; k < NITER; ++k) {
            const int cur = k & 1;
#pragma unroll
            for (int p = 0; p < 4; ++p) {
                int r = aRow + p * 32;
                __nv_bfloat162 h0 = __floats2bfloat162_rn(av[p].x, av[p].y);
                __nv_bfloat162 h1 = __floats2bfloat162_rn(av[p].z, av[p].w);
                *reinterpret_cast<__nv_bfloat162*>(&Ash[cur][r*APITCH + aKv*4    ]) = h0;
                *reinterpret_cast<__nv_bfloat162*>(&Ash[cur][r*APITCH + aKv*4 + 2]) = h1;
            }
            *reinterpret_cast<int4*>(&Bsh[cur][bN*APITCH + bKv*8]) = bv;
            __syncthreads();

            if (k + 1 < NITER) {
                const int kb = (k + 1) * BK;
#pragma unroll
                for (int p = 0; p < 4; ++p)
                    av[p] = *reinterpret_cast<const float4*>(
                        F + (size_t)(rowBase + aRow + p*32) * H_ + kb + aKv * 4);
                bv = *reinterpret_cast<const int4*>(g_Wt + bN*H_ + kb + bKv*8);
            }

#pragma unroll
            for (int ks = 0; ks < 2; ++ks) {
                uint32_t afr[2][4], bfr[4][2];
                const int c = ks*16 + tq*2;
#pragma unroll
                for (int mi = 0; mi < 2; ++mi) {
                    int r = wm*32 + mi*16 + g;
                    afr[mi][0] = *reinterpret_cast<const uint32_t*>(&Ash[cur][ r     *APITCH + c    ]);
                    afr[mi][1] = *reinterpret_cast<const uint32_t*>(&Ash[cur][(r + 8)*APITCH + c    ]);
                    afr[mi][2] = *reinterpret_cast<const uint32_t*>(&Ash[cur][ r     *APITCH + c + 8]);
                    afr[mi][3] = *reinterpret_cast<const uint32_t*>(&Ash[cur][(r + 8)*APITCH + c + 8]);
                }
#pragma unroll
                for (int ni = 0; ni < 4; ++ni) {
                    int n = wn*32 + ni*8 + g;
                    bfr[ni][0] = *reinterpret_cast<const uint32_t*>(&Bsh[cur][n*APITCH + c    ]);
                    bfr[ni][1] = *reinterpret_cast<const uint32_t*>(&Bsh[cur][n*APITCH + c + 8]);
                }
#pragma unroll
                for (int mi = 0; mi < 2; ++mi)
#pragma unroll
                    for (int ni = 0; ni < 4; ++ni) {
                        asm volatile(
                            "mma.sync.aligned.m16n8k16.row.col.f32.bf16.bf16.f32 "
                            "{%0,%1,%2,%3}, {%4,%5,%6,%7}, {%8,%9}, {%0,%1,%2,%3};"
                            : "+f"(acc[mi][ni][0]), "+f"(acc[mi][ni][1]),
                              "+f"(acc[mi][ni][2]), "+f"(acc[mi][ni][3])
                            : "r"(afr[mi][0]), "r"(afr[mi][1]), "r"(afr[mi][2]), "r"(afr[mi][3]),
                              "r"(bfr[ni][0]), "r"(bfr[ni][1]));
                    }
            }
            __syncthreads();
        }

#pragma unroll
        for (int mi = 0; mi < 2; ++mi) {
#pragma unroll
            for (int ni = 0; ni < 4; ++ni) {
                int col = wn*32 + ni*8 + tq*2;
                float b0 = bias[col], b1 = bias[col + 1];
                int r0 = rowBase + wm*32 + mi*16 + g;
                float2 v0 = make_float2((acc[mi][ni][0] + b0) * LOG2E,
                                        (acc[mi][ni][1] + b1) * LOG2E);
                float2 v1 = make_float2((acc[mi][ni][2] + b0) * LOG2E,
                                        (acc[mi][ni][3] + b1) * LOG2E);
                *reinterpret_cast<float2*>(&g_emit2[(size_t) r0      * K_ + col]) = v0;
                *reinterpret_cast<float2*>(&g_emit2[(size_t)(r0 + 8) * K_ + col]) = v1;
            }
        }
    }

    // ================= handoff =================
    const int b = blockIdx.x >> 2;
    __threadfence();                 // release this block's emit tile
    __syncthreads();
    if (tid == 0) s_owner = (atomicAdd(&g_cnt[b], 1) == 3);
    __syncthreads();
    if (!s_owner) return;
    __threadfence();                 // acquire peer tiles

    // ================= CRF phase (owner block only) =================
    const int len = g_len[b];
    const int*   tg = g_tags + (size_t)b * L_;
    const float* eb = g_emit2 + (size_t)b * L_ * K_;

    // ---- gold path score with all 256 threads ----
    {
        float sc = 0.f;
        for (int t = tid; t < len; t += 256) {
            int kt = tg[t];
            sc += eb[t * K_ + kt];
            if (t >= 1) sc += g_Tt2[kt * K_ + tg[t - 1]];
        }
#pragma unroll
        for (int o = 16; o > 0; o >>= 1) sc += __shfl_xor_sync(0xffffffffu, sc, o);
        if (lane == 0) s_red[warp] = sc;
        __syncthreads();
        if (tid == 0) {
            float s = 0.f;
#pragma unroll
            for (int i = 0; i < 8; ++i) s += s_red[i];
            s_score = s;
        }
        __syncthreads();
    }

    if (tid >= 128) return;          // recursion: warps 0-3 (bar.sync 1,128)
    const int j    = tid >> 1;       // output state
    const int half = tid & 1;        // source half (32 states)

    // ---- E half-rows in registers: Erow[i] = 2^(T2[half*32+i][j]-6) ----
    float Erow[32];
    {
        const float4* tp = reinterpret_cast<const float4*>(g_Et + j * K_ + half * 32);
#pragma unroll
        for (int q = 0; q < 8; ++q) {
            float4 v = tp[q];
            Erow[4*q] = v.x; Erow[4*q+1] = v.y; Erow[4*q+2] = v.z; Erow[4*q+3] = v.w;
        }
    }

    if (half == 0) ds[0][j] = ex2f(eb[j]);
    float C = 0.f;
    float ebuf[8];
#pragma unroll
    for (int q = 0; q < 8; ++q) ebuf[q] = eb[(q + 1) * K_ + j];   // len >= 128
    BAR128();

    int cur = 0;

    auto STEP = [&](int t, int slot, bool renorm, bool use_ring) {
        float ev;
        if (use_ring) {
            ev = ebuf[slot];
            int tn = t + 8; if (tn > L_ - 1) tn = L_ - 1;
            ebuf[slot] = eb[tn * K_ + j];
        } else {
            ev = eb[t * K_ + j];
        }
        const float se = ex2f(ev);

        const float4* p4 = reinterpret_cast<const float4*>(&ds[cur][half * 32]);
        float a0=0.f, a1=0.f, a2=0.f, a3=0.f;
        float mA = 0.f, mB = 0.f;     // streamed max over own half (values >= 0)
#pragma unroll
        for (int q = 0; q < 8; ++q) {
            float4 v = p4[q];
            a0 = fmaf(v.x, Erow[4*q    ], a0);
            a1 = fmaf(v.y, Erow[4*q + 1], a1);
            a2 = fmaf(v.z, Erow[4*q + 2], a2);
            a3 = fmaf(v.w, Erow[4*q + 3], a3);
            if (renorm) {
                float mv = fmaxf(fmaxf(v.x, v.y), fmaxf(v.z, v.w));
                if (q & 1) mB = fmaxf(mB, mv); else mA = fmaxf(mA, mv);
            }
        }
        float acc = (a0 + a1) + (a2 + a3);
        acc += __shfl_xor_sync(0xffffffffu, acc, 1);   // combine halves
        float dn = acc * se;

        if (renorm) {
            float m = fmaxf(mA, mB);
            m = fmaxf(m, __shfl_xor_sync(0xffffffffu, m, 1));  // full 64-state max
            m = fmaxf(m, 1e-30f);
            dn *= rcpf(m);
            C += lg2f(m);
        }
        if (half == 0) ds[cur ^ 1][j] = dn;
        BAR128();
        cur ^= 1;
    };

    // head peel t=1..7
#pragma unroll
    for (int t = 1; t <= 7; ++t) STEP(t, t - 1, false, true);

    // main chunks of 8 (renorm at i==0 -> t % 8 == 0)
    int tb = 8;
    for (; tb + 8 <= len; tb += 8) {
#pragma unroll
        for (int i = 0; i < 8; ++i)
            STEP(tb + i, (i + 7) & 7, i == 0, true);
    }
    // tail: direct loads
    for (int t = tb; t < len; ++t)
        STEP(t, 0, (t & 7) == 0, false);

    // ---- final logsumexp over 64 states ----
    float v = (half == 0) ? ds[cur][j] : 0.f;
#pragma unroll
    for (int o = 16; o > 0; o >>= 1) v += __shfl_xor_sync(0xffffffffu, v, o);
    if (lane == 0) s_red[warp] = v;   // warps 0..3
    BAR128();
    if (tid == 0) {
        const float S = (s_red[0] + s_red[1]) + (s_red[2] + s_red[3]);
        const float logz2 = C + ESHIFT * (float)(len - 1) + lg2f(S);
        out[b] = (logz2 - s_score) * LN2;
    }
}

// ---------------------------------------------------------------
extern "C" void kernel_launch(void* const* d_in, const int* in_sizes, int n_in,
                              void* d_out, int out_size)
{
    const float*         features = (const float*)d_in[0];
    const float*         W        = (const float*)d_in[1];
    const float*         bias     = (const float*)d_in[2];
    const float*         trans    = (const float*)d_in[3];
    const int*           tagsraw  = (const int*)d_in[4];
    const unsigned char* maskraw  = (const unsigned char*)d_in[5];
    float*               out      = (float*)d_out;

    detect_kernel<<<1, 256>>>((const unsigned int*)tagsraw, maskraw);
    convert_kernel<<<B_, 256>>>(tagsraw, maskraw, W, trans);
    fused_kernel<<<M_ / BM, 256>>>(features, bias, out);
}

// round 10
// speedup vs baseline: 1.2742x; 1.2334x over previous
#include <cuda_runtime.h>
#include <cuda_bf16.h>
#include <cstdint>

#define B_ 256
#define L_ 512
#define H_ 768
#define K_ 64
#define M_ (B_*L_)

#define LOG2E 1.4426950408889634f
#define LN2   0.6931471805599453f
#define ESHIFT 6.0f

// -------- device scratch --------
__device__ float          g_emit2[M_*K_];     // emit * log2(e)
__device__ float          g_Tt2[K_*K_];       // Tt2[j][k] = T[k][j]*log2e (gold score)
__device__ float          g_Et[K_*K_];        // Et[j][i]  = 2^(T[i][j]*log2e - 6)
__device__ __nv_bfloat16  g_Wt[K_*H_];        // W^T bf16 [n][h]
__device__ int            g_tags[M_];
__device__ int            g_len[B_];
__device__ int            g_cnt[B_];          // per-batch tile completion counter
__device__ int            g_maskmode;

__device__ __forceinline__ float ex2f(float x){ float y; asm("ex2.approx.ftz.f32 %0, %1;" : "=f"(y) : "f"(x)); return y; }
__device__ __forceinline__ float lg2f(float x){ float y; asm("lg2.approx.f32 %0, %1;"     : "=f"(y) : "f"(x)); return y; }
__device__ __forceinline__ float rcpf(float x){ float y; asm("rcp.approx.ftz.f32 %0, %1;" : "=f"(y) : "f"(x)); return y; }
#define BAR64() asm volatile("bar.sync 1, 64;" ::: "memory")

// ---------------------------------------------------------------
// convert: self-detect dtypes, canonicalize tags, lengths, W/T prep.
__global__ __launch_bounds__(256)
void convert_kernel(const int* __restrict__ tagsraw,
                    const unsigned char* __restrict__ maskraw,
                    const float* __restrict__ W,
                    const float* __restrict__ T)
{
    __shared__ int s_red[8];
    const int b   = blockIdx.x;
    const int tid = threadIdx.x;

    if (tid == 0) g_cnt[b] = 0;            // reset handoff counters every replay

    // dtype self-detect on the FIRST 512 words (in-bounds for both dtypes):
    // int64 tags (<64) -> all odd words zero; int32 -> P[all zero] = 64^-256.
    unsigned int w = ((const unsigned int*)tagsraw)[2 * tid + 1];
    const int tm = __syncthreads_or(w != 0) ? 0 : 1;
    // mask: batch 0 has len>=128; 1-byte mask => byte[1]==1; 4-byte (int/float) => 0.
    const int mm = (maskraw[1] != 0) ? 0 : 1;

    for (int t = tid; t < L_; t += 256) {
        long idx = (long)b * L_ + t;
        g_tags[idx] = (tm == 1) ? tagsraw[2 * idx] : tagsraw[idx];
    }
    int cnt = 0;
    if (mm == 0) {
        const unsigned char* mb = maskraw + (size_t)b * L_;
        for (int t = tid; t < L_; t += 256) cnt += (mb[t] != 0);
    } else {
        const unsigned int* mw = ((const unsigned int*)maskraw) + (size_t)b * L_;
        for (int t = tid; t < L_; t += 256) cnt += (mw[t] != 0);
    }
#pragma unroll
    for (int o = 16; o > 0; o >>= 1) cnt += __shfl_xor_sync(0xffffffffu, cnt, o);
    if ((tid & 31) == 0) s_red[tid >> 5] = cnt;
    __syncthreads();
    if (tid == 0) {
        int s = 0;
#pragma unroll
        for (int i = 0; i < 8; ++i) s += s_red[i];
        g_len[b] = s;
    }

    // ---- prep, strided across the whole grid ----
    const int gidx    = b * 256 + tid;
    const int gstride = B_ * 256;
    for (int i = gidx; i < K_*H_; i += gstride) {
        int n = i / H_, h = i - n*H_;
        g_Wt[i] = __float2bfloat16(W[h*K_ + n]);
    }
    for (int i = gidx; i < K_*K_; i += gstride) {
        int j = i >> 6, k = i & 63;
        float t2 = T[k*K_ + j] * LOG2E;
        g_Tt2[i] = t2;
        g_Et[i]  = ex2f(t2 - ESHIFT);
    }
}

// ---------------------------------------------------------------
// FUSED kernel: GEMM tile (blocks 4b..4b+3 cover batch b); the block that
// completes the batch's 4th tile runs the CRF (R6-proven 64-thread version).
// GEMM: BK=64, dynamic smem double buffer, 2 blocks/SM pinned.
#define BM      128
#define BK      64
#define NITER   (H_/BK)   // 12
#define APITCH  72        // bf16 per smem row: frag banks (4g+tq)%32 distinct
#define ASTAGE  (BM*APITCH)
#define BSTAGE  (K_*APITCH)
#define SMEM_DYN ((2*ASTAGE + 2*BSTAGE) * 2)   // bytes (bf16)

__global__ __launch_bounds__(256, 2)
void fused_kernel(const float* __restrict__ F, const float* __restrict__ bias,
                  float* __restrict__ out)
{
    extern __shared__ __nv_bfloat16 smx[];
    __shared__ float s_red[8];
    __shared__ float ds0[K_], ds1[K_];
    __shared__ float s_score;
    __shared__ int   s_owner;

    __nv_bfloat16* AshB = smx;                 // 2 stages of BM x BK
    __nv_bfloat16* BshB = smx + 2*ASTAGE;      // 2 stages of K_ x BK

    const int tid  = threadIdx.x;
    const int lane = tid & 31;
    const int warp = tid >> 5;
    const int wm   = warp & 3;
    const int wn   = warp >> 2;
    const int rowBase = blockIdx.x * BM;

    // ================= GEMM phase =================
    {
        float acc[2][4][4];
#pragma unroll
        for (int mi = 0; mi < 2; ++mi)
#pragma unroll
            for (int ni = 0; ni < 4; ++ni)
#pragma unroll
                for (int q = 0; q < 4; ++q) acc[mi][ni][q] = 0.f;

        const int aRow = tid >> 4;     // 0..15, rows aRow+16p
        const int aCv  = tid & 15;     // float4 col within BK=64
        const int bN   = tid >> 2;     // 0..63
        const int bKv  = tid & 3;
        const int g  = lane >> 2;
        const int tq = lane & 3;

        float4 av[8];
        int4   bv[2];
#pragma unroll
        for (int p = 0; p < 8; ++p)
            av[p] = *reinterpret_cast<const float4*>(
                F + (size_t)(rowBase + aRow + 16*p) * H_ + aCv * 4);
#pragma unroll
        for (int p = 0; p < 2; ++p)
            bv[p] = *reinterpret_cast<const int4*>(g_Wt + bN*H_ + bKv*8 + 32*p);

#pragma unroll 1
        for (int k = 0; k < NITER; ++k) {
            __nv_bfloat16* Ac = AshB + (k & 1) * ASTAGE;
            __nv_bfloat16* Bc = BshB + (k & 1) * BSTAGE;

#pragma unroll
            for (int p = 0; p < 8; ++p) {
                int r = aRow + 16*p;
                __nv_bfloat162 h0 = __floats2bfloat162_rn(av[p].x, av[p].y);
                __nv_bfloat162 h1 = __floats2bfloat162_rn(av[p].z, av[p].w);
                uint2 pk = make_uint2(*reinterpret_cast<unsigned*>(&h0),
                                      *reinterpret_cast<unsigned*>(&h1));
                *reinterpret_cast<uint2*>(&Ac[r*APITCH + aCv*4]) = pk;  // STS.64, conflict-free
            }
#pragma unroll
            for (int p = 0; p < 2; ++p)
                *reinterpret_cast<int4*>(&Bc[bN*APITCH + bKv*8 + 32*p]) = bv[p];
            __syncthreads();

            if (k + 1 < NITER) {
                const int kb = (k + 1) * BK;
#pragma unroll
                for (int p = 0; p < 8; ++p)
                    av[p] = *reinterpret_cast<const float4*>(
                        F + (size_t)(rowBase + aRow + 16*p) * H_ + kb + aCv * 4);
#pragma unroll
                for (int p = 0; p < 2; ++p)
                    bv[p] = *reinterpret_cast<const int4*>(g_Wt + bN*H_ + kb + bKv*8 + 32*p);
            }

#pragma unroll
            for (int ks = 0; ks < 4; ++ks) {
                uint32_t afr[2][4], bfr[4][2];
                const int c = ks*16 + tq*2;
#pragma unroll
                for (int mi = 0; mi < 2; ++mi) {
                    int r = wm*32 + mi*16 + g;
                    afr[mi][0] = *reinterpret_cast<const uint32_t*>(&Ac[ r     *APITCH + c    ]);
                    afr[mi][1] = *reinterpret_cast<const uint32_t*>(&Ac[(r + 8)*APITCH + c    ]);
                    afr[mi][2] = *reinterpret_cast<const uint32_t*>(&Ac[ r     *APITCH + c + 8]);
                    afr[mi][3] = *reinterpret_cast<const uint32_t*>(&Ac[(r + 8)*APITCH + c + 8]);
                }
#pragma unroll
                for (int ni = 0; ni < 4; ++ni) {
                    int n = wn*32 + ni*8 + g;
                    bfr[ni][0] = *reinterpret_cast<const uint32_t*>(&Bc[n*APITCH + c    ]);
                    bfr[ni][1] = *reinterpret_cast<const uint32_t*>(&Bc[n*APITCH + c + 8]);
                }
#pragma unroll
                for (int mi = 0; mi < 2; ++mi)
#pragma unroll
                    for (int ni = 0; ni < 4; ++ni) {
                        asm volatile(
                            "mma.sync.aligned.m16n8k16.row.col.f32.bf16.bf16.f32 "
                            "{%0,%1,%2,%3}, {%4,%5,%6,%7}, {%8,%9}, {%0,%1,%2,%3};"
                            : "+f"(acc[mi][ni][0]), "+f"(acc[mi][ni][1]),
                              "+f"(acc[mi][ni][2]), "+f"(acc[mi][ni][3])
                            : "r"(afr[mi][0]), "r"(afr[mi][1]), "r"(afr[mi][2]), "r"(afr[mi][3]),
                              "r"(bfr[ni][0]), "r"(bfr[ni][1]));
                    }
            }
            __syncthreads();
        }

        const int g2  = lane >> 2;
        const int tq2 = lane & 3;
#pragma unroll
        for (int mi = 0; mi < 2; ++mi) {
#pragma unroll
            for (int ni = 0; ni < 4; ++ni) {
                int col = wn*32 + ni*8 + tq2*2;
                float b0 = bias[col], b1 = bias[col + 1];
                int r0 = rowBase + wm*32 + mi*16 + g2;
                float2 v0 = make_float2((acc[mi][ni][0] + b0) * LOG2E,
                                        (acc[mi][ni][1] + b1) * LOG2E);
                float2 v1 = make_float2((acc[mi][ni][2] + b0) * LOG2E,
                                        (acc[mi][ni][3] + b1) * LOG2E);
                *reinterpret_cast<float2*>(&g_emit2[(size_t) r0      * K_ + col]) = v0;
                *reinterpret_cast<float2*>(&g_emit2[(size_t)(r0 + 8) * K_ + col]) = v1;
            }
        }
    }

    // ================= handoff =================
    const int b = blockIdx.x >> 2;
    __threadfence();                 // release this block's emit tile
    __syncthreads();
    if (tid == 0) s_owner = (atomicAdd(&g_cnt[b], 1) == 3);
    __syncthreads();
    if (!s_owner) return;
    __threadfence();                 // acquire peer tiles

    // ================= CRF phase (owner block only, R6-proven) =================
    const int len = g_len[b];
    const int*   tg = g_tags + (size_t)b * L_;
    const float* eb = g_emit2 + (size_t)b * L_ * K_;

    // ---- gold path score with all 256 threads ----
    {
        float sc = 0.f;
        for (int t = tid; t < len; t += 256) {
            int kt = tg[t];
            sc += eb[t * K_ + kt];
            if (t >= 1) sc += g_Tt2[kt * K_ + tg[t - 1]];
        }
#pragma unroll
        for (int o = 16; o > 0; o >>= 1) sc += __shfl_xor_sync(0xffffffffu, sc, o);
        if (lane == 0) s_red[warp] = sc;
        __syncthreads();
        if (tid == 0) {
            float s = 0.f;
#pragma unroll
            for (int i = 0; i < 8; ++i) s += s_red[i];
            s_score = s;
        }
        __syncthreads();
    }

    if (tid >= 64) return;           // recursion: warps 0-1 (bar.sync 1,64)
    const int j = tid;

    // ---- all 64 E coefficients in registers ----
    float Erow[64];
    {
        const float4* ep = reinterpret_cast<const float4*>(g_Et + j * K_);
#pragma unroll
        for (int q = 0; q < 16; ++q) {
            float4 v = ep[q];
            Erow[4*q] = v.x; Erow[4*q+1] = v.y; Erow[4*q+2] = v.z; Erow[4*q+3] = v.w;
        }
    }

    ds0[j] = ex2f(eb[j]);
    float C = 0.f;
    float ebuf[8];
#pragma unroll
    for (int q = 0; q < 8; ++q) ebuf[q] = eb[(q + 1) * K_ + j];   // len >= 128
    BAR64();

    int cur = 0;

    auto STEP = [&](int t, int slot, bool renorm, bool use_ring) {
        float ev;
        if (use_ring) {
            ev = ebuf[slot];
            int tn = t + 8; if (tn > L_ - 1) tn = L_ - 1;
            ebuf[slot] = eb[tn * K_ + j];
        } else {
            ev = eb[t * K_ + j];
        }
        const float se = ex2f(ev);

        const float4* p4 = reinterpret_cast<const float4*>(cur ? ds1 : ds0);  // broadcast
        float a0=0.f,a1=0.f,a2=0.f,a3=0.f,a4=0.f,a5=0.f,a6=0.f,a7=0.f;
        float mA = 0.f, mB = 0.f;
#pragma unroll
        for (int q = 0; q < 16; ++q) {
            float4 v = p4[q];
            if (q & 1) {
                a4 = fmaf(v.x, Erow[4*q    ], a4);
                a5 = fmaf(v.y, Erow[4*q + 1], a5);
                a6 = fmaf(v.z, Erow[4*q + 2], a6);
                a7 = fmaf(v.w, Erow[4*q + 3], a7);
            } else {
                a0 = fmaf(v.x, Erow[4*q    ], a0);
                a1 = fmaf(v.y, Erow[4*q + 1], a1);
                a2 = fmaf(v.z, Erow[4*q + 2], a2);
                a3 = fmaf(v.w, Erow[4*q + 3], a3);
            }
            if (renorm) {
                float mv = fmaxf(fmaxf(v.x, v.y), fmaxf(v.z, v.w));
                if (q & 1) mB = fmaxf(mB, mv); else mA = fmaxf(mA, mv);
            }
        }
        float acc = ((a0+a1) + (a2+a3)) + ((a4+a5) + (a6+a7));
        float dn = acc * se;

        if (renorm) {
            float m = fmaxf(fmaxf(mA, mB), 1e-30f);  // exact block max of d_{t-1}
            dn *= rcpf(m);
            C += lg2f(m);
        }
        (cur ? ds0 : ds1)[j] = dn;
        BAR64();
        cur ^= 1;
    };

    // head peel t=1..7
#pragma unroll
    for (int t = 1; t <= 7; ++t) STEP(t, t - 1, false, true);

    // main chunks of 8 (renorm at i==0 -> t % 8 == 0)
    int tb = 8;
    for (; tb + 8 <= len; tb += 8) {
#pragma unroll
        for (int i = 0; i < 8; ++i)
            STEP(tb + i, (i + 7) & 7, i == 0, true);
    }
    // tail: direct loads
    for (int t = tb; t < len; ++t)
        STEP(t, 0, (t & 7) == 0, false);

    // ---- final logsumexp over the 64 states ----
    float v = (cur ? ds1 : ds0)[j];
#pragma unroll
    for (int o = 16; o > 0; o >>= 1) v += __shfl_xor_sync(0xffffffffu, v, o);
    if (lane == 0) s_red[warp] = v;
    BAR64();
    if (tid == 0) {
        const float S = s_red[0] + s_red[1];
        const float logz2 = C + ESHIFT * (float)(len - 1) + lg2f(S);
        out[b] = (logz2 - s_score) * LN2;
    }
}

// ---------------------------------------------------------------
extern "C" void kernel_launch(void* const* d_in, const int* in_sizes, int n_in,
                              void* d_out, int out_size)
{
    const float*         features = (const float*)d_in[0];
    const float*         W        = (const float*)d_in[1];
    const float*         bias     = (const float*)d_in[2];
    const float*         trans    = (const float*)d_in[3];
    const int*           tagsraw  = (const int*)d_in[4];
    const unsigned char* maskraw  = (const unsigned char*)d_in[5];
    float*               out      = (float*)d_out;

    static int attr_done = 0;
    if (!attr_done) {
        cudaFuncSetAttribute(fused_kernel,
                             cudaFuncAttributeMaxDynamicSharedMemorySize, SMEM_DYN);
        attr_done = 1;
    }

    convert_kernel<<<B_, 256>>>(tagsraw, maskraw, W, trans);
    fused_kernel<<<M_ / BM, 256, SMEM_DYN>>>(features, bias, out);
}

// round 11
// speedup vs baseline: 1.3620x; 1.0689x over previous
#include <cuda_runtime.h>
#include <cuda_bf16.h>
#include <cstdint>

#define B_ 256
#define L_ 512
#define H_ 768
#define K_ 64
#define M_ (B_*L_)

#define LOG2E 1.4426950408889634f
#define LN2   0.6931471805599453f
#define ESHIFT 6.0f

// -------- device scratch --------
__device__ float          g_emit2[M_*K_];     // emit * log2(e)
__device__ float          g_Tt2[K_*K_];       // Tt2[j][k] = T[k][j]*log2e (gold score)
__device__ float          g_Et[K_*K_];        // Et[j][i]  = 2^(T[i][j]*log2e - 6)
__device__ __nv_bfloat16  g_Wt[K_*H_];        // W^T bf16 [n][h]
__device__ int            g_tags[M_];
__device__ int            g_len[B_];
__device__ int            g_cnt[B_];          // per-batch tile completion counter

__device__ __forceinline__ float ex2f(float x){ float y; asm("ex2.approx.ftz.f32 %0, %1;" : "=f"(y) : "f"(x)); return y; }
__device__ __forceinline__ float lg2f(float x){ float y; asm("lg2.approx.f32 %0, %1;"     : "=f"(y) : "f"(x)); return y; }
__device__ __forceinline__ float rcpf(float x){ float y; asm("rcp.approx.ftz.f32 %0, %1;" : "=f"(y) : "f"(x)); return y; }
#define BAR64() asm volatile("bar.sync 1, 64;" ::: "memory")

#define CP_ASYNC16(sa, gp) asm volatile("cp.async.cg.shared.global [%0], [%1], 16;" :: "r"(sa), "l"(gp) : "memory")
#define CP_COMMIT()        asm volatile("cp.async.commit_group;" ::: "memory")
#define CP_WAIT1()         asm volatile("cp.async.wait_group 1;" ::: "memory")

__device__ __forceinline__ void ldsm_x4(uint32_t& r0, uint32_t& r1, uint32_t& r2, uint32_t& r3,
                                        uint32_t addr)
{
    asm volatile("ldmatrix.sync.aligned.m8n8.x4.shared.b16 {%0,%1,%2,%3}, [%4];"
                 : "=r"(r0), "=r"(r1), "=r"(r2), "=r"(r3) : "r"(addr));
}

// ---------------------------------------------------------------
// convert: self-detect dtypes, canonicalize tags, lengths, W/T prep.
__global__ __launch_bounds__(256)
void convert_kernel(const int* __restrict__ tagsraw,
                    const unsigned char* __restrict__ maskraw,
                    const float* __restrict__ W,
                    const float* __restrict__ T)
{
    __shared__ int s_red[8];
    const int b   = blockIdx.x;
    const int tid = threadIdx.x;

    if (tid == 0) g_cnt[b] = 0;            // reset handoff counters every replay

    // dtype self-detect (first 512 tag words, in-bounds under both dtypes)
    unsigned int w = ((const unsigned int*)tagsraw)[2 * tid + 1];
    const int tm = __syncthreads_or(w != 0) ? 0 : 1;
    const int mm = (maskraw[1] != 0) ? 0 : 1;

    for (int t = tid; t < L_; t += 256) {
        long idx = (long)b * L_ + t;
        g_tags[idx] = (tm == 1) ? tagsraw[2 * idx] : tagsraw[idx];
    }
    int cnt = 0;
    if (mm == 0) {
        const unsigned char* mb = maskraw + (size_t)b * L_;
        for (int t = tid; t < L_; t += 256) cnt += (mb[t] != 0);
    } else {
        const unsigned int* mw = ((const unsigned int*)maskraw) + (size_t)b * L_;
        for (int t = tid; t < L_; t += 256) cnt += (mw[t] != 0);
    }
#pragma unroll
    for (int o = 16; o > 0; o >>= 1) cnt += __shfl_xor_sync(0xffffffffu, cnt, o);
    if ((tid & 31) == 0) s_red[tid >> 5] = cnt;
    __syncthreads();
    if (tid == 0) {
        int s = 0;
#pragma unroll
        for (int i = 0; i < 8; ++i) s += s_red[i];
        g_len[b] = s;
    }

    // ---- prep, strided across the whole grid ----
    const int gidx    = b * 256 + tid;
    const int gstride = B_ * 256;
    for (int i = gidx; i < K_*H_; i += gstride) {
        int n = i / H_, h = i - n*H_;
        g_Wt[i] = __float2bfloat16(W[h*K_ + n]);
    }
    for (int i = gidx; i < K_*K_; i += gstride) {
        int j = i >> 6, k = i & 63;
        float t2 = T[k*K_ + j] * LOG2E;
        g_Tt2[i] = t2;
        g_Et[i]  = ex2f(t2 - ESHIFT);
    }
}

// ---------------------------------------------------------------
// FUSED kernel: GEMM tile (blocks 4b..4b+3 per batch b) + CRF by owner block.
// GEMM: BK=64, dynamic smem double buffer, ldmatrix fragments, cp.async B.
#define BM      128
#define BK      64
#define NITER   (H_/BK)   // 12
#define APITCH  72        // bf16 per smem row (144B): LDSM rows hit distinct banks
#define ASTAGE  (BM*APITCH)
#define BSTAGE  (K_*APITCH)
#define SMEM_DYN ((2*ASTAGE + 2*BSTAGE) * 2)   // bytes

__global__ __launch_bounds__(256, 2)
void fused_kernel(const float* __restrict__ F, const float* __restrict__ bias,
                  float* __restrict__ out)
{
    extern __shared__ __nv_bfloat16 smx[];
    __shared__ float s_red[8];
    __shared__ float ds0[K_], ds1[K_];
    __shared__ float s_score;
    __shared__ int   s_owner;

    __nv_bfloat16* AshB = smx;                 // 2 stages BM x BK
    __nv_bfloat16* BshB = smx + 2*ASTAGE;      // 2 stages K_ x BK

    const int tid  = threadIdx.x;
    const int lane = tid & 31;
    const int warp = tid >> 5;
    const int wm   = warp & 3;
    const int wn   = warp >> 2;
    const int rowBase = blockIdx.x * BM;

    // ================= GEMM phase =================
    {
        float acc[2][4][4];
#pragma unroll
        for (int mi = 0; mi < 2; ++mi)
#pragma unroll
            for (int ni = 0; ni < 4; ++ni)
#pragma unroll
                for (int q = 0; q < 4; ++q) acc[mi][ni][q] = 0.f;

        const int aRow = tid >> 4;     // 0..15, rows aRow+16p
        const int aCv  = tid & 15;     // float4 col within BK=64
        // B cp.async mapping: 16B chunks; chunk = tid + 256p -> row=chunk>>3, c16=chunk&7
        const int bRow = tid >> 3;     // 0..31 (+32 for p=1)
        const int bC16 = tid & 7;

        // ldmatrix per-lane address components
        const int lrA = wm*32 + (lane & 15);            // + mi*16
        const int lcA = (lane >> 4) * 8;                // + ks*16
        const int lrB = wn*32 + ((lane >> 4) & 1) * 8 + (lane & 7);   // + np*16
        const int lcB = ((lane >> 3) & 1) * 8;          // + ks*16

        uint32_t aBase[2], bBase[2], bDst[2];
#pragma unroll
        for (int s = 0; s < 2; ++s) {
            aBase[s] = (uint32_t)__cvta_generic_to_shared(AshB + s*ASTAGE) ;
            bBase[s] = (uint32_t)__cvta_generic_to_shared(BshB + s*BSTAGE);
            bDst[s]  = (uint32_t)__cvta_generic_to_shared(BshB + s*BSTAGE + bRow*APITCH + bC16*8);
        }
        const __nv_bfloat16* gB = g_Wt + (size_t)bRow * H_ + bC16*8;

        float4 av[8];
#pragma unroll
        for (int p = 0; p < 8; ++p)
            av[p] = *reinterpret_cast<const float4*>(
                F + (size_t)(rowBase + aRow + 16*p) * H_ + aCv * 4);
        // prologue: B stage 0
#pragma unroll
        for (int p = 0; p < 2; ++p)
            CP_ASYNC16(bDst[0] + p * 32 * APITCH * 2, gB + (size_t)p * 32 * H_);
        CP_COMMIT();

#pragma unroll 1
        for (int k = 0; k < NITER; ++k) {
            const int cur = k & 1;
            __nv_bfloat16* Ac = AshB + cur * ASTAGE;

            // stage A (f32 regs -> bf16 smem)
#pragma unroll
            for (int p = 0; p < 8; ++p) {
                int r = aRow + 16*p;
                __nv_bfloat162 h0 = __floats2bfloat162_rn(av[p].x, av[p].y);
                __nv_bfloat162 h1 = __floats2bfloat162_rn(av[p].z, av[p].w);
                uint2 pk = make_uint2(*reinterpret_cast<unsigned*>(&h0),
                                      *reinterpret_cast<unsigned*>(&h1));
                *reinterpret_cast<uint2*>(&Ac[r*APITCH + aCv*4]) = pk;
            }
            // issue B for stage k+1
            if (k + 1 < NITER) {
                const int kb = (k + 1) * BK;
#pragma unroll
                for (int p = 0; p < 2; ++p)
                    CP_ASYNC16(bDst[(k+1) & 1] + p * 32 * APITCH * 2,
                               gB + (size_t)p * 32 * H_ + kb);
            }
            CP_COMMIT();          // uniform group counting (empty on last iter)
            CP_WAIT1();           // B stage k resident
            __syncthreads();      // A+B stage k visible to all

            if (k + 1 < NITER) {  // reload A regs for k+1
                const int kb = (k + 1) * BK;
#pragma unroll
                for (int p = 0; p < 8; ++p)
                    av[p] = *reinterpret_cast<const float4*>(
                        F + (size_t)(rowBase + aRow + 16*p) * H_ + kb + aCv * 4);
            }

            const uint32_t aB = aBase[cur];
            const uint32_t bB = bBase[cur];
#pragma unroll
            for (int ks = 0; ks < 4; ++ks) {
                uint32_t afr[2][4], bfr[4][2];
#pragma unroll
                for (int mi = 0; mi < 2; ++mi) {
                    uint32_t addr = aB + (uint32_t)(((lrA + mi*16)*APITCH + ks*16 + lcA) * 2);
                    ldsm_x4(afr[mi][0], afr[mi][1], afr[mi][2], afr[mi][3], addr);
                }
#pragma unroll
                for (int np = 0; np < 2; ++np) {
                    uint32_t addr = bB + (uint32_t)(((lrB + np*16)*APITCH + ks*16 + lcB) * 2);
                    ldsm_x4(bfr[np*2][0], bfr[np*2][1], bfr[np*2+1][0], bfr[np*2+1][1], addr);
                }
#pragma unroll
                for (int mi = 0; mi < 2; ++mi)
#pragma unroll
                    for (int ni = 0; ni < 4; ++ni) {
                        asm volatile(
                            "mma.sync.aligned.m16n8k16.row.col.f32.bf16.bf16.f32 "
                            "{%0,%1,%2,%3}, {%4,%5,%6,%7}, {%8,%9}, {%0,%1,%2,%3};"
                            : "+f"(acc[mi][ni][0]), "+f"(acc[mi][ni][1]),
                              "+f"(acc[mi][ni][2]), "+f"(acc[mi][ni][3])
                            : "r"(afr[mi][0]), "r"(afr[mi][1]), "r"(afr[mi][2]), "r"(afr[mi][3]),
                              "r"(bfr[ni][0]), "r"(bfr[ni][1]));
                    }
            }
            __syncthreads();      // WAR: stage reuse at k+2
        }

        const int g2  = lane >> 2;
        const int tq2 = lane & 3;
#pragma unroll
        for (int mi = 0; mi < 2; ++mi) {
#pragma unroll
            for (int ni = 0; ni < 4; ++ni) {
                int col = wn*32 + ni*8 + tq2*2;
                float b0 = bias[col], b1 = bias[col + 1];
                int r0 = rowBase + wm*32 + mi*16 + g2;
                float2 v0 = make_float2((acc[mi][ni][0] + b0) * LOG2E,
                                        (acc[mi][ni][1] + b1) * LOG2E);
                float2 v1 = make_float2((acc[mi][ni][2] + b0) * LOG2E,
                                        (acc[mi][ni][3] + b1) * LOG2E);
                *reinterpret_cast<float2*>(&g_emit2[(size_t) r0      * K_ + col]) = v0;
                *reinterpret_cast<float2*>(&g_emit2[(size_t)(r0 + 8) * K_ + col]) = v1;
            }
        }
    }

    // ================= handoff =================
    const int b = blockIdx.x >> 2;
    __threadfence();
    __syncthreads();
    if (tid == 0) s_owner = (atomicAdd(&g_cnt[b], 1) == 3);
    __syncthreads();
    if (!s_owner) return;
    __threadfence();

    // ================= CRF phase (owner block only, R6/R10-proven) ============
    const int len = g_len[b];
    const int*   tg = g_tags + (size_t)b * L_;
    const float* eb = g_emit2 + (size_t)b * L_ * K_;

    {
        float sc = 0.f;
        for (int t = tid; t < len; t += 256) {
            int kt = tg[t];
            sc += eb[t * K_ + kt];
            if (t >= 1) sc += g_Tt2[kt * K_ + tg[t - 1]];
        }
#pragma unroll
        for (int o = 16; o > 0; o >>= 1) sc += __shfl_xor_sync(0xffffffffu, sc, o);
        if (lane == 0) s_red[warp] = sc;
        __syncthreads();
        if (tid == 0) {
            float s = 0.f;
#pragma unroll
            for (int i = 0; i < 8; ++i) s += s_red[i];
            s_score = s;
        }
        __syncthreads();
    }

    if (tid >= 64) return;
    const int j = tid;

    float Erow[64];
    {
        const float4* ep = reinterpret_cast<const float4*>(g_Et + j * K_);
#pragma unroll
        for (int q = 0; q < 16; ++q) {
            float4 v = ep[q];
            Erow[4*q] = v.x; Erow[4*q+1] = v.y; Erow[4*q+2] = v.z; Erow[4*q+3] = v.w;
        }
    }

    ds0[j] = ex2f(eb[j]);
    float C = 0.f;
    float ebuf[8];
#pragma unroll
    for (int q = 0; q < 8; ++q) ebuf[q] = eb[(q + 1) * K_ + j];   // len >= 128
    BAR64();

    int cur = 0;

    auto STEP = [&](int t, int slot, bool renorm, bool use_ring) {
        float ev;
        if (use_ring) {
            ev = ebuf[slot];
            int tn = t + 8; if (tn > L_ - 1) tn = L_ - 1;
            ebuf[slot] = eb[tn * K_ + j];
        } else {
            ev = eb[t * K_ + j];
        }
        const float se = ex2f(ev);

        const float4* p4 = reinterpret_cast<const float4*>(cur ? ds1 : ds0);
        float a0=0.f,a1=0.f,a2=0.f,a3=0.f,a4=0.f,a5=0.f,a6=0.f,a7=0.f;
        float mA = 0.f, mB = 0.f;
#pragma unroll
        for (int q = 0; q < 16; ++q) {
            float4 v = p4[q];
            if (q & 1) {
                a4 = fmaf(v.x, Erow[4*q    ], a4);
                a5 = fmaf(v.y, Erow[4*q + 1], a5);
                a6 = fmaf(v.z, Erow[4*q + 2], a6);
                a7 = fmaf(v.w, Erow[4*q + 3], a7);
            } else {
                a0 = fmaf(v.x, Erow[4*q    ], a0);
                a1 = fmaf(v.y, Erow[4*q + 1], a1);
                a2 = fmaf(v.z, Erow[4*q + 2], a2);
                a3 = fmaf(v.w, Erow[4*q + 3], a3);
            }
            if (renorm) {
                float mv = fmaxf(fmaxf(v.x, v.y), fmaxf(v.z, v.w));
                if (q & 1) mB = fmaxf(mB, mv); else mA = fmaxf(mA, mv);
            }
        }
        float acc = ((a0+a1) + (a2+a3)) + ((a4+a5) + (a6+a7));
        float dn = acc * se;

        if (renorm) {
            float m = fmaxf(fmaxf(mA, mB), 1e-30f);
            dn *= rcpf(m);
            C += lg2f(m);
        }
        (cur ? ds0 : ds1)[j] = dn;
        BAR64();
        cur ^= 1;
    };

#pragma unroll
    for (int t = 1; t <= 7; ++t) STEP(t, t - 1, false, true);

    int tb = 8;
    for (; tb + 8 <= len; tb += 8) {
#pragma unroll
        for (int i = 0; i < 8; ++i)
            STEP(tb + i, (i + 7) & 7, i == 0, true);
    }
    for (int t = tb; t < len; ++t)
        STEP(t, 0, (t & 7) == 0, false);

    float v = (cur ? ds1 : ds0)[j];
#pragma unroll
    for (int o = 16; o > 0; o >>= 1) v += __shfl_xor_sync(0xffffffffu, v, o);
    if (lane == 0) s_red[warp] = v;
    BAR64();
    if (tid == 0) {
        const float S = s_red[0] + s_red[1];
        const float logz2 = C + ESHIFT * (float)(len - 1) + lg2f(S);
        out[b] = (logz2 - s_score) * LN2;
    }
}

// ---------------------------------------------------------------
extern "C" void kernel_launch(void* const* d_in, const int* in_sizes, int n_in,
                              void* d_out, int out_size)
{
    const float*         features = (const float*)d_in[0];
    const float*         W        = (const float*)d_in[1];
    const float*         bias     = (const float*)d_in[2];
    const float*         trans    = (const float*)d_in[3];
    const int*           tagsraw  = (const int*)d_in[4];
    const unsigned char* maskraw  = (const unsigned char*)d_in[5];
    float*               out      = (float*)d_out;

    static int attr_done = 0;
    if (!attr_done) {
        cudaFuncSetAttribute(fused_kernel,
                             cudaFuncAttributeMaxDynamicSharedMemorySize, SMEM_DYN);
        attr_done = 1;
    }

    convert_kernel<<<B_, 256>>>(tagsraw, maskraw, W, trans);
    fused_kernel<<<M_ / BM, 256, SMEM_DYN>>>(features, bias, out);
}